// round 1
// baseline (speedup 1.0000x reference)
#include <cuda_runtime.h>
#include <cuda_bf16.h>

// Causal cumulative normalization: out[b,f,t] = (x - cummean) / sqrt(cumvar + EPS)
// along the last (frames) axis. Rows are independent: one warp per row.
//
// Per iteration a warp processes 128 contiguous frames (float4 per lane):
//   - per-lane prefix over its 4 elements (sum and sum-of-squares)
//   - warp-wide inclusive shuffle scan of the lane totals
//   - register carry across iterations
// Reciprocal frame counts (1/(t+1)) come from a precomputed __device__ table
// (16 KB, L1-resident) to avoid a per-element MUFU.RCP.

#define EPSV 1e-4f

constexpr int FRAMES = 4000;
constexpr int CHUNK  = 128;               // frames per warp per iteration
constexpr int NFULL  = FRAMES / CHUNK;    // 31 full iterations
// remainder = 4000 - 31*128 = 32 (exactly one element per lane)

__device__ float g_inv[FRAMES];

__global__ void init_inv_kernel() {
    int i = blockIdx.x * blockDim.x + threadIdx.x;
    if (i < FRAMES) g_inv[i] = 1.0f / (float)(i + 1);
}

__global__ __launch_bounds__(256)
void cumnorm_kernel(const float* __restrict__ x, float* __restrict__ out, int rows) {
    int gw   = (blockIdx.x * blockDim.x + threadIdx.x) >> 5;
    int lane = threadIdx.x & 31;
    if (gw >= rows) return;

    const float* __restrict__ xr  = x   + (long long)gw * FRAMES;
    float*       __restrict__ outr = out + (long long)gw * FRAMES;

    float carry_s = 0.0f, carry_q = 0.0f;

    // software prefetch of first chunk
    float4 v = *reinterpret_cast<const float4*>(xr    + lane * 4);
    float4 w = *reinterpret_cast<const float4*>(g_inv + lane * 4);

    #pragma unroll 1
    for (int it = 0; it < NFULL; ++it) {
        float4 cv = v, cw = w;
        if (it + 1 < NFULL) {
            int nb = (it + 1) * CHUNK + lane * 4;
            v = *reinterpret_cast<const float4*>(xr    + nb);
            w = *reinterpret_cast<const float4*>(g_inv + nb);
        }

        // per-lane inclusive prefixes over 4 elements
        float s0 = cv.x;
        float s1 = s0 + cv.y;
        float s2 = s1 + cv.z;
        float s3 = s2 + cv.w;
        float q0 = cv.x * cv.x;
        float q1 = fmaf(cv.y, cv.y, q0);
        float q2 = fmaf(cv.z, cv.z, q1);
        float q3 = fmaf(cv.w, cv.w, q2);

        // warp inclusive scan of lane totals (sum, sumsq)
        float ts = s3, tq = q3;
        #pragma unroll
        for (int off = 1; off < 32; off <<= 1) {
            float as = __shfl_up_sync(0xffffffffu, ts, off);
            float aq = __shfl_up_sync(0xffffffffu, tq, off);
            if (lane >= off) { ts += as; tq += aq; }
        }

        // exclusive lane base + carry (lane 0: ts - s3 == 0 exactly)
        float bs = carry_s + (ts - s3);
        float bq = carry_q + (tq - q3);
        carry_s += __shfl_sync(0xffffffffu, ts, 31);
        carry_q += __shfl_sync(0xffffffffu, tq, 31);

        float4 o;
        {
            float sum = bs + s0, qq = bq + q0;
            float mean = sum * cw.x;
            float var  = fmaf(qq, cw.x, -mean * mean);
            o.x = (cv.x - mean) * rsqrtf(var + EPSV);
        }
        {
            float sum = bs + s1, qq = bq + q1;
            float mean = sum * cw.y;
            float var  = fmaf(qq, cw.y, -mean * mean);
            o.y = (cv.y - mean) * rsqrtf(var + EPSV);
        }
        {
            float sum = bs + s2, qq = bq + q2;
            float mean = sum * cw.z;
            float var  = fmaf(qq, cw.z, -mean * mean);
            o.z = (cv.z - mean) * rsqrtf(var + EPSV);
        }
        {
            float sum = bs + s3, qq = bq + q3;
            float mean = sum * cw.w;
            float var  = fmaf(qq, cw.w, -mean * mean);
            o.w = (cv.w - mean) * rsqrtf(var + EPSV);
        }
        *reinterpret_cast<float4*>(outr + it * CHUNK + lane * 4) = o;
    }

    // remainder: 32 frames, one scalar element per lane
    {
        int base = NFULL * CHUNK + lane;
        float xv = xr[base];
        float wi = g_inv[base];
        float ts = xv, tq = xv * xv;
        #pragma unroll
        for (int off = 1; off < 32; off <<= 1) {
            float as = __shfl_up_sync(0xffffffffu, ts, off);
            float aq = __shfl_up_sync(0xffffffffu, tq, off);
            if (lane >= off) { ts += as; tq += aq; }
        }
        float sum  = carry_s + ts;
        float qq   = carry_q + tq;
        float mean = sum * wi;
        float var  = fmaf(qq, wi, -mean * mean);
        outr[base] = (xv - mean) * rsqrtf(var + EPSV);
    }
}

extern "C" void kernel_launch(void* const* d_in, const int* in_sizes, int n_in,
                              void* d_out, int out_size) {
    const float* x = (const float*)d_in[0];
    float* out = (float*)d_out;
    int rows = in_sizes[0] / FRAMES;   // 32*512 = 16384

    init_inv_kernel<<<(FRAMES + 255) / 256, 256>>>();

    constexpr int WARPS_PER_BLOCK = 8;
    int blocks = (rows + WARPS_PER_BLOCK - 1) / WARPS_PER_BLOCK;
    cumnorm_kernel<<<blocks, WARPS_PER_BLOCK * 32>>>(x, out, rows);
}

// round 4
// speedup vs baseline: 1.1264x; 1.1264x over previous
#include <cuda_runtime.h>
#include <cuda_bf16.h>

// Causal cumulative normalization along frames. One warp per row.
// 256-frame chunks (2 x float4 per lane), 1-chunk-deep software prefetch
// (=> 4 outstanding LDG.128 per warp, 256-frame prefetch distance),
// warp shuffle scan with register carry. 1/count from an L1-resident table.

#define EPSV 1e-4f

constexpr int FRAMES   = 4000;
constexpr int F4_ROW   = FRAMES / 4;      // 1000 float4 per row
constexpr int NFULL256 = 15;              // 15 * 256 = 3840 frames
// then one 128-frame chunk (3840..3967), then 32-frame tail (3968..3999)

__device__ float g_inv[FRAMES];

__global__ void init_inv_kernel() {
    int i = blockIdx.x * blockDim.x + threadIdx.x;
    if (i < FRAMES) g_inv[i] = 1.0f / (float)(i + 1);
}

__device__ __forceinline__ void process128(float4 cv, float4 cw, int lane,
                                           float& carry_s, float& carry_q,
                                           float4* outp) {
    // per-lane inclusive prefixes over 4 elements
    float s0 = cv.x;
    float s1 = s0 + cv.y;
    float s2 = s1 + cv.z;
    float s3 = s2 + cv.w;
    float q0 = cv.x * cv.x;
    float q1 = fmaf(cv.y, cv.y, q0);
    float q2 = fmaf(cv.z, cv.z, q1);
    float q3 = fmaf(cv.w, cv.w, q2);

    // warp inclusive scan of lane totals
    float ts = s3, tq = q3;
    #pragma unroll
    for (int off = 1; off < 32; off <<= 1) {
        float as = __shfl_up_sync(0xffffffffu, ts, off);
        float aq = __shfl_up_sync(0xffffffffu, tq, off);
        if (lane >= off) { ts += as; tq += aq; }
    }

    float bs = carry_s + (ts - s3);   // exclusive lane base + carry
    float bq = carry_q + (tq - q3);
    carry_s += __shfl_sync(0xffffffffu, ts, 31);
    carry_q += __shfl_sync(0xffffffffu, tq, 31);

    float4 o;
    {
        float sum = bs + s0, qq = bq + q0;
        float mean = sum * cw.x;
        float var  = fmaf(qq, cw.x, -mean * mean);
        o.x = (cv.x - mean) * rsqrtf(var + EPSV);
    }
    {
        float sum = bs + s1, qq = bq + q1;
        float mean = sum * cw.y;
        float var  = fmaf(qq, cw.y, -mean * mean);
        o.y = (cv.y - mean) * rsqrtf(var + EPSV);
    }
    {
        float sum = bs + s2, qq = bq + q2;
        float mean = sum * cw.z;
        float var  = fmaf(qq, cw.z, -mean * mean);
        o.z = (cv.z - mean) * rsqrtf(var + EPSV);
    }
    {
        float sum = bs + s3, qq = bq + q3;
        float mean = sum * cw.w;
        float var  = fmaf(qq, cw.w, -mean * mean);
        o.w = (cv.w - mean) * rsqrtf(var + EPSV);
    }
    __stcs(outp, o);
}

__global__ __launch_bounds__(256)
void cumnorm_kernel(const float* __restrict__ x, float* __restrict__ out, int rows) {
    int gw   = (blockIdx.x * blockDim.x + threadIdx.x) >> 5;
    int lane = threadIdx.x & 31;
    if (gw >= rows) return;

    const float4* __restrict__ xv = (const float4*)(x + (long long)gw * FRAMES);
    float4*       __restrict__ ov = (float4*)(out + (long long)gw * FRAMES);
    const float4* __restrict__ wv = (const float4*)g_inv;

    float carry_s = 0.0f, carry_q = 0.0f;

    // prefetch first 256-frame chunk
    float4 v0 = __ldcs(xv + lane);
    float4 v1 = __ldcs(xv + 32 + lane);
    float4 w0 = wv[lane];
    float4 w1 = wv[32 + lane];

    #pragma unroll 1
    for (int it = 0; it < NFULL256; ++it) {
        float4 cv0 = v0, cv1 = v1, cw0 = w0, cw1 = w1;
        if (it + 1 < NFULL256) {
            int nb = (it + 1) * 64 + lane;
            v0 = __ldcs(xv + nb);
            v1 = __ldcs(xv + nb + 32);
            w0 = wv[nb];
            w1 = wv[nb + 32];
        } else {
            // prefetch the trailing 128-frame chunk into slot 0
            v0 = __ldcs(xv + NFULL256 * 64 + lane);
            w0 = wv[NFULL256 * 64 + lane];
        }
        process128(cv0, cw0, lane, carry_s, carry_q, ov + it * 64 + lane);
        process128(cv1, cw1, lane, carry_s, carry_q, ov + it * 64 + 32 + lane);
    }

    // trailing 128-frame chunk (frames 3840..3967), already prefetched in v0/w0
    process128(v0, w0, lane, carry_s, carry_q, ov + NFULL256 * 64 + lane);

    // 32-frame tail (frames 3968..3999), one scalar element per lane
    {
        int base = NFULL256 * 256 + 128 + lane;
        const float* xr = (const float*)xv;
        float xval = __ldcs(xr + base);
        float wi = g_inv[base];
        float ts = xval, tq = xval * xval;
        #pragma unroll
        for (int off = 1; off < 32; off <<= 1) {
            float as = __shfl_up_sync(0xffffffffu, ts, off);
            float aq = __shfl_up_sync(0xffffffffu, tq, off);
            if (lane >= off) { ts += as; tq += aq; }
        }
        float sum  = carry_s + ts;
        float qq   = carry_q + tq;
        float mean = sum * wi;
        float var  = fmaf(qq, wi, -mean * mean);
        float o = (xval - mean) * rsqrtf(var + EPSV);
        __stcs((float*)ov + base, o);
    }
}

extern "C" void kernel_launch(void* const* d_in, const int* in_sizes, int n_in,
                              void* d_out, int out_size) {
    const float* x = (const float*)d_in[0];
    float* out = (float*)d_out;
    int rows = in_sizes[0] / FRAMES;   // 32*512 = 16384

    init_inv_kernel<<<(FRAMES + 255) / 256, 256>>>();

    constexpr int WARPS_PER_BLOCK = 8;
    int blocks = (rows + WARPS_PER_BLOCK - 1) / WARPS_PER_BLOCK;
    cumnorm_kernel<<<blocks, WARPS_PER_BLOCK * 32>>>(x, out, rows);
}

// round 5
// speedup vs baseline: 1.1569x; 1.0271x over previous
#include <cuda_runtime.h>
#include <cuda_bf16.h>

// Causal cumulative normalization along frames. One warp per row.
// 256-frame chunks (2 x float4 per lane), 1-chunk-deep software prefetch,
// warp shuffle scan with register carry.
//
// Division-free reformulation (no reciprocal table, no extra L1 traffic):
//   out = (x*c - s) * rsqrt(c*(q + eps*c) - s*s)
// where s = cumsum, q = cumsum of squares, c = frame count (exact small float).

#define EPSV 1e-4f

constexpr int FRAMES   = 4000;
constexpr int NFULL256 = 15;              // 15 * 256 = 3840 frames
// then one 128-frame chunk (3840..3967), then 32-frame tail (3968..3999)

__device__ __forceinline__ void process128(float4 cv, float cbase, int lane,
                                           float& carry_s, float& carry_q,
                                           float4* outp) {
    // per-lane inclusive prefixes over 4 elements
    float s0 = cv.x;
    float s1 = s0 + cv.y;
    float s2 = s1 + cv.z;
    float s3 = s2 + cv.w;
    float q0 = cv.x * cv.x;
    float q1 = fmaf(cv.y, cv.y, q0);
    float q2 = fmaf(cv.z, cv.z, q1);
    float q3 = fmaf(cv.w, cv.w, q2);

    // warp inclusive scan of lane totals
    float ts = s3, tq = q3;
    #pragma unroll
    for (int off = 1; off < 32; off <<= 1) {
        float as = __shfl_up_sync(0xffffffffu, ts, off);
        float aq = __shfl_up_sync(0xffffffffu, tq, off);
        if (lane >= off) { ts += as; tq += aq; }
    }

    float bs = carry_s + (ts - s3);   // exclusive lane base + carry
    float bq = carry_q + (tq - q3);
    carry_s += __shfl_sync(0xffffffffu, ts, 31);
    carry_q += __shfl_sync(0xffffffffu, tq, 31);

    float4 o;
    {
        float c = cbase;
        float s = bs + s0, q = bq + q0;
        float u = fmaf(EPSV, c, q);
        float r = fmaf(c, u, -s * s);
        float t = fmaf(cv.x, c, -s);
        o.x = t * rsqrtf(r);
    }
    {
        float c = cbase + 1.0f;
        float s = bs + s1, q = bq + q1;
        float u = fmaf(EPSV, c, q);
        float r = fmaf(c, u, -s * s);
        float t = fmaf(cv.y, c, -s);
        o.y = t * rsqrtf(r);
    }
    {
        float c = cbase + 2.0f;
        float s = bs + s2, q = bq + q2;
        float u = fmaf(EPSV, c, q);
        float r = fmaf(c, u, -s * s);
        float t = fmaf(cv.z, c, -s);
        o.z = t * rsqrtf(r);
    }
    {
        float c = cbase + 3.0f;
        float s = bs + s3, q = bq + q3;
        float u = fmaf(EPSV, c, q);
        float r = fmaf(c, u, -s * s);
        float t = fmaf(cv.w, c, -s);
        o.w = t * rsqrtf(r);
    }
    __stcs(outp, o);
}

__global__ __launch_bounds__(256, 6)
void cumnorm_kernel(const float* __restrict__ x, float* __restrict__ out, int rows) {
    int gw   = (blockIdx.x * blockDim.x + threadIdx.x) >> 5;
    int lane = threadIdx.x & 31;
    if (gw >= rows) return;

    const float4* __restrict__ xv = (const float4*)(x + (long long)gw * FRAMES);
    float4*       __restrict__ ov = (float4*)(out + (long long)gw * FRAMES);

    float carry_s = 0.0f, carry_q = 0.0f;

    // count of the first element handled by this lane within a chunk
    float clane = (float)(lane * 4 + 1);

    // prefetch first 256-frame chunk
    float4 v0 = __ldcs(xv + lane);
    float4 v1 = __ldcs(xv + 32 + lane);

    #pragma unroll 1
    for (int it = 0; it < NFULL256; ++it) {
        float4 cv0 = v0, cv1 = v1;
        if (it + 1 < NFULL256) {
            int nb = (it + 1) * 64 + lane;
            v0 = __ldcs(xv + nb);
            v1 = __ldcs(xv + nb + 32);
        } else {
            // prefetch the trailing 128-frame chunk into slot 0
            v0 = __ldcs(xv + NFULL256 * 64 + lane);
        }
        float cbase = (float)(it * 256) + clane;
        process128(cv0, cbase,          lane, carry_s, carry_q, ov + it * 64 + lane);
        process128(cv1, cbase + 128.0f, lane, carry_s, carry_q, ov + it * 64 + 32 + lane);
    }

    // trailing 128-frame chunk (frames 3840..3967), already prefetched in v0
    process128(v0, 3840.0f + clane, lane, carry_s, carry_q, ov + NFULL256 * 64 + lane);

    // 32-frame tail (frames 3968..3999), one scalar element per lane
    {
        int base = NFULL256 * 256 + 128 + lane;
        const float* xr = (const float*)xv;
        float xval = __ldcs(xr + base);
        float ts = xval, tq = xval * xval;
        #pragma unroll
        for (int off = 1; off < 32; off <<= 1) {
            float as = __shfl_up_sync(0xffffffffu, ts, off);
            float aq = __shfl_up_sync(0xffffffffu, tq, off);
            if (lane >= off) { ts += as; tq += aq; }
        }
        float c = (float)(base + 1);
        float s = carry_s + ts;
        float q = carry_q + tq;
        float u = fmaf(EPSV, c, q);
        float r = fmaf(c, u, -s * s);
        float t = fmaf(xval, c, -s);
        __stcs((float*)ov + base, t * rsqrtf(r));
    }
}

extern "C" void kernel_launch(void* const* d_in, const int* in_sizes, int n_in,
                              void* d_out, int out_size) {
    const float* x = (const float*)d_in[0];
    float* out = (float*)d_out;
    int rows = in_sizes[0] / FRAMES;   // 32*512 = 16384

    constexpr int WARPS_PER_BLOCK = 8;
    int blocks = (rows + WARPS_PER_BLOCK - 1) / WARPS_PER_BLOCK;
    cumnorm_kernel<<<blocks, WARPS_PER_BLOCK * 32>>>(x, out, rows);
}

// round 6
// speedup vs baseline: 1.2000x; 1.0372x over previous
#include <cuda_runtime.h>
#include <cuda_bf16.h>

// Causal cumulative normalization along frames.
// TWO consecutive rows per warp (contiguous 32KB region, 2 independent scan
// chains for ILP/MLP, and near-integral wave count: 2048 blocks of 128 thr,
// 7 blocks/SM resident -> 1.98 waves instead of 2.31).
// Per row per iteration: 256 frames (2 x float4 per lane), 1-chunk prefetch.
// Division-free: out = (x*c - s) * rsqrt(c*(q + eps*c) - s*s).

#define EPSV 1e-4f

constexpr int FRAMES   = 4000;
constexpr int NFULL256 = 15;              // 15 * 256 = 3840 frames
// then one 128-frame chunk (3840..3967), then 32-frame tail (3968..3999)

__device__ __forceinline__ void process128(float4 cv, float cbase, int lane,
                                           float& carry_s, float& carry_q,
                                           float4* outp) {
    // per-lane inclusive prefixes over 4 elements
    float s0 = cv.x;
    float s1 = s0 + cv.y;
    float s2 = s1 + cv.z;
    float s3 = s2 + cv.w;
    float q0 = cv.x * cv.x;
    float q1 = fmaf(cv.y, cv.y, q0);
    float q2 = fmaf(cv.z, cv.z, q1);
    float q3 = fmaf(cv.w, cv.w, q2);

    // warp inclusive scan of lane totals
    float ts = s3, tq = q3;
    #pragma unroll
    for (int off = 1; off < 32; off <<= 1) {
        float as = __shfl_up_sync(0xffffffffu, ts, off);
        float aq = __shfl_up_sync(0xffffffffu, tq, off);
        if (lane >= off) { ts += as; tq += aq; }
    }

    float bs = carry_s + (ts - s3);   // exclusive lane base + carry
    float bq = carry_q + (tq - q3);
    carry_s += __shfl_sync(0xffffffffu, ts, 31);
    carry_q += __shfl_sync(0xffffffffu, tq, 31);

    float4 o;
    {
        float c = cbase;
        float s = bs + s0, q = bq + q0;
        float u = fmaf(EPSV, c, q);
        float r = fmaf(c, u, -s * s);
        o.x = fmaf(cv.x, c, -s) * rsqrtf(r);
    }
    {
        float c = cbase + 1.0f;
        float s = bs + s1, q = bq + q1;
        float u = fmaf(EPSV, c, q);
        float r = fmaf(c, u, -s * s);
        o.y = fmaf(cv.y, c, -s) * rsqrtf(r);
    }
    {
        float c = cbase + 2.0f;
        float s = bs + s2, q = bq + q2;
        float u = fmaf(EPSV, c, q);
        float r = fmaf(c, u, -s * s);
        o.z = fmaf(cv.z, c, -s) * rsqrtf(r);
    }
    {
        float c = cbase + 3.0f;
        float s = bs + s3, q = bq + q3;
        float u = fmaf(EPSV, c, q);
        float r = fmaf(c, u, -s * s);
        o.w = fmaf(cv.w, c, -s) * rsqrtf(r);
    }
    __stcs(outp, o);
}

__device__ __forceinline__ void tail32(const float* xr, float* outr, int lane,
                                       float carry_s, float carry_q) {
    int base = NFULL256 * 256 + 128 + lane;   // 3968 + lane
    float xval = __ldcs(xr + base);
    float ts = xval, tq = xval * xval;
    #pragma unroll
    for (int off = 1; off < 32; off <<= 1) {
        float as = __shfl_up_sync(0xffffffffu, ts, off);
        float aq = __shfl_up_sync(0xffffffffu, tq, off);
        if (lane >= off) { ts += as; tq += aq; }
    }
    float c = (float)(base + 1);
    float s = carry_s + ts;
    float q = carry_q + tq;
    float u = fmaf(EPSV, c, q);
    float r = fmaf(c, u, -s * s);
    __stcs(outr + base, fmaf(xval, c, -s) * rsqrtf(r));
}

__global__ __launch_bounds__(128, 7)
void cumnorm_kernel(const float* __restrict__ x, float* __restrict__ out, int pairs) {
    int gw   = (blockIdx.x * blockDim.x + threadIdx.x) >> 5;
    int lane = threadIdx.x & 31;
    if (gw >= pairs) return;

    const float4* __restrict__ xa = (const float4*)(x + (long long)(2 * gw)     * FRAMES);
    const float4* __restrict__ xb = (const float4*)(x + (long long)(2 * gw + 1) * FRAMES);
    float4*       __restrict__ oa = (float4*)(out + (long long)(2 * gw)     * FRAMES);
    float4*       __restrict__ ob = (float4*)(out + (long long)(2 * gw + 1) * FRAMES);

    float csa = 0.0f, cqa = 0.0f;   // carries row A
    float csb = 0.0f, cqb = 0.0f;   // carries row B

    float clane = (float)(lane * 4 + 1);

    // prefetch first 256-frame chunk of both rows
    float4 a0 = __ldcs(xa + lane);
    float4 a1 = __ldcs(xa + 32 + lane);
    float4 b0 = __ldcs(xb + lane);
    float4 b1 = __ldcs(xb + 32 + lane);

    #pragma unroll 1
    for (int it = 0; it < NFULL256; ++it) {
        float4 ca0 = a0, ca1 = a1, cb0 = b0, cb1 = b1;
        if (it + 1 < NFULL256) {
            int nb = (it + 1) * 64 + lane;
            a0 = __ldcs(xa + nb);
            a1 = __ldcs(xa + nb + 32);
            b0 = __ldcs(xb + nb);
            b1 = __ldcs(xb + nb + 32);
        } else {
            // prefetch the trailing 128-frame chunks into slot 0
            a0 = __ldcs(xa + NFULL256 * 64 + lane);
            b0 = __ldcs(xb + NFULL256 * 64 + lane);
        }
        float cbase = (float)(it * 256) + clane;
        process128(ca0, cbase,          lane, csa, cqa, oa + it * 64 + lane);
        process128(cb0, cbase,          lane, csb, cqb, ob + it * 64 + lane);
        process128(ca1, cbase + 128.0f, lane, csa, cqa, oa + it * 64 + 32 + lane);
        process128(cb1, cbase + 128.0f, lane, csb, cqb, ob + it * 64 + 32 + lane);
    }

    // trailing 128-frame chunks (frames 3840..3967), prefetched in a0/b0
    process128(a0, 3840.0f + clane, lane, csa, cqa, oa + NFULL256 * 64 + lane);
    process128(b0, 3840.0f + clane, lane, csb, cqb, ob + NFULL256 * 64 + lane);

    // 32-frame tails (frames 3968..3999)
    tail32((const float*)xa, (float*)oa, lane, csa, cqa);
    tail32((const float*)xb, (float*)ob, lane, csb, cqb);
}

extern "C" void kernel_launch(void* const* d_in, const int* in_sizes, int n_in,
                              void* d_out, int out_size) {
    const float* x = (const float*)d_in[0];
    float* out = (float*)d_out;
    int rows  = in_sizes[0] / FRAMES;   // 32*512 = 16384
    int pairs = rows / 2;               // 8192 (rows is even here)

    constexpr int WARPS_PER_BLOCK = 4;  // 128-thread blocks for fine scheduling
    int blocks = (pairs + WARPS_PER_BLOCK - 1) / WARPS_PER_BLOCK;
    cumnorm_kernel<<<blocks, WARPS_PER_BLOCK * 32>>>(x, out, pairs);
}